// round 7
// baseline (speedup 1.0000x reference)
#include <cuda_runtime.h>
#include <cuda_bf16.h>
#include <cstdint>

#define DEV_INLINE __device__ __forceinline__

constexpr int L_   = 100;
constexpr int B_   = 32;
constexpr int E_   = 512;
constexpr int F_   = 256;
constexpr int M_   = 128;
constexpr int D_   = 258;
constexpr int NPAIR = L_ * L_;                 // 10000
constexpr int NTILE = (NPAIR + 127) / 128;     // 79

// ---------------- scratch (device globals; no allocation allowed) ----------------
__device__ float g_act1[B_ * F_ * L_];
__device__ float g_act2[B_ * F_ * L_];
__device__ float g_aff[4][2 * F_];             // per layer: [a (F)], [b (F)]
__device__ float g_A[B_ * L_ * M_];
__device__ float g_C[B_ * L_ * M_];
__device__ float g_hb[B_ * M_];
__device__ float g_part[B_ * NTILE * M_];
// transposed packed weights: [layer][hl][n*128+k] bf16 (hl: 0=hi, 1=lo)
__device__ __align__(16) uint16_t g_wpackT[3][2][128 * 128];
// transposed conv weights: wT[(e*3+k)*256 + f]
__device__ float g_cwT1[E_ * 3 * F_];          // layer 1 (EIN=512)
__device__ float g_cwT2[3][F_ * 3 * F_];       // layers 2..4 (EIN=256)

DEV_INLINE float lrelu(float z) { return fmaxf(z, 0.f) + 0.1f * fminf(z, 0.f); }

DEV_INLINE void split_pack2(float x0, float x1, uint32_t& hi, uint32_t& lo) {
    __nv_bfloat16 h0 = __float2bfloat16(x0);
    __nv_bfloat16 h1 = __float2bfloat16(x1);
    float r0 = x0 - __bfloat162float(h0);
    float r1 = x1 - __bfloat162float(h1);
    __nv_bfloat16 l0 = __float2bfloat16(r0);
    __nv_bfloat16 l1 = __float2bfloat16(r1);
    hi = ((uint32_t)__bfloat16_as_ushort(h1) << 16) | (uint32_t)__bfloat16_as_ushort(h0);
    lo = ((uint32_t)__bfloat16_as_ushort(l1) << 16) | (uint32_t)__bfloat16_as_ushort(l0);
}

DEV_INLINE void mma16816(float c[4], const uint32_t a[4], uint32_t b0, uint32_t b1) {
    asm volatile(
        "mma.sync.aligned.m16n8k16.row.col.f32.bf16.bf16.f32 "
        "{%0,%1,%2,%3}, {%4,%5,%6,%7}, {%8,%9}, {%0,%1,%2,%3};"
        : "+f"(c[0]), "+f"(c[1]), "+f"(c[2]), "+f"(c[3])
        : "r"(a[0]), "r"(a[1]), "r"(a[2]), "r"(a[3]), "r"(b0), "r"(b1));
}

// =================================================================================
// Pack conv weights transposed: wT[(e*3+k)*F + f] = w[f][e][k]
// =================================================================================
__global__ void __launch_bounds__(256) pack_convw(
    const float* __restrict__ cw1, const float* __restrict__ cw2,
    const float* __restrict__ cw3, const float* __restrict__ cw4)
{
    const int tid = blockIdx.x * 256 + threadIdx.x;
    const int stride = gridDim.x * 256;
    for (int i = tid; i < F_ * E_ * 3; i += stride) {
        int r = i >> 8;            // output-major: coalesced writes
        int f = i & 255;
        g_cwT1[i] = cw1[(size_t)f * (E_ * 3) + r];
    }
    for (int layer = 0; layer < 3; layer++) {
        const float* cw = layer == 0 ? cw2 : (layer == 1 ? cw3 : cw4);
        for (int i = tid; i < F_ * F_ * 3; i += stride) {
            int r = i >> 8;
            int f = i & 255;
            g_cwT2[layer][i] = cw[(size_t)f * (F_ * 3) + r];
        }
    }
}

// =================================================================================
// Conv1d v2 (K=3, pad 1) + bias + leakyReLU.  Register-tiled:
// block = 64 threads, 16 output channels, one batch, all 100 positions.
// thread = 4 f x 7 l; weights via 3x LDG.128/e from transposed wT (resolved
// in DEVICE code via wsel); input chunk (32 e) staged in smem with previous
// layer's BN affine folded in.
// =================================================================================
constexpr int EC = 32;    // e-chunk
constexpr int LP = 114;   // padded l extent (16 groups * 7 + 2 halo)

template <int EIN, bool FIRST>
__global__ void __launch_bounds__(64) conv2_kernel(
    const float* __restrict__ in_ext, int src, int aff_layer,
    int wsel,                         // <0 -> g_cwT1 ; else g_cwT2[wsel]
    const float* __restrict__ cb, int dst)
{
    __shared__ float in_s[EC][LP];

    const int b  = blockIdx.x;
    const int f0 = blockIdx.y * 16;
    const int t  = threadIdx.x;
    const int tf = (t & 3) * 4;       // f sub-offset: 0,4,8,12
    const int l0 = (t >> 2) * 7;      // 0..105

    const float* wT  = (wsel < 0) ? g_cwT1 : g_cwT2[wsel];
    const float* in  = FIRST ? in_ext : (src ? g_act2 : g_act1);
    float*       out = dst ? g_act2 : g_act1;
    const float* aff_a = g_aff[aff_layer];
    const float* aff_b = g_aff[aff_layer] + F_;

    float acc[4][7];
#pragma unroll
    for (int fi = 0; fi < 4; fi++)
#pragma unroll
        for (int j = 0; j < 7; j++) acc[fi][j] = 0.f;

    for (int e0 = 0; e0 < EIN; e0 += EC) {
        __syncthreads();
        // ---- stage input chunk (halo shifted by -1, zero padded) ----
        for (int c = t; c < EC * LP; c += 64) {
            int e, lo;
            if (FIRST) { e = c & (EC - 1); lo = c >> 5; }      // coalesced over e
            else       { e = c / LP;       lo = c - e * LP; }  // coalesced over l
            int l = lo - 1;
            float v = 0.f;
            if (l >= 0 && l < L_ && lo < LP) {
                if (FIRST) {
                    v = in[(size_t)l * (B_ * E_) + (size_t)b * E_ + (e0 + e)];
                } else {
                    v = in[((size_t)b * EIN + (e0 + e)) * L_ + l];
                    v = aff_a[e0 + e] * v + aff_b[e0 + e];
                }
            }
            if (lo < LP) in_s[e][lo] = v;
        }
        __syncthreads();

        const float* wp = wT + (size_t)e0 * 3 * F_ + f0 + tf;
#pragma unroll 4
        for (int e = 0; e < EC; e++) {
            float4 w0 = *(const float4*)(wp + (size_t)e * (3 * F_));
            float4 w1 = *(const float4*)(wp + (size_t)e * (3 * F_) + F_);
            float4 w2 = *(const float4*)(wp + (size_t)e * (3 * F_) + 2 * F_);
            float wk[3][4] = {{w0.x, w0.y, w0.z, w0.w},
                              {w1.x, w1.y, w1.z, w1.w},
                              {w2.x, w2.y, w2.z, w2.w}};
            float x[9];
#pragma unroll
            for (int i = 0; i < 9; i++) x[i] = in_s[e][l0 + i];
#pragma unroll
            for (int fi = 0; fi < 4; fi++)
#pragma unroll
                for (int j = 0; j < 7; j++)
                    acc[fi][j] += x[j] * wk[0][fi] + x[j + 1] * wk[1][fi]
                                + x[j + 2] * wk[2][fi];
        }
    }

#pragma unroll
    for (int fi = 0; fi < 4; fi++) {
        int f = f0 + tf + fi;
        float bb = cb[f];
        float* op = out + ((size_t)b * F_ + f) * L_;
#pragma unroll
        for (int j = 0; j < 7; j++) {
            int l = l0 + j;
            if (l < L_) op[l] = lrelu(acc[fi][j] + bb);
        }
    }
}

// =================================================================================
// BN stats (unchanged)
// =================================================================================
__global__ void __launch_bounds__(128) stats_kernel(
    int src, int layer,
    const float* __restrict__ gamma, const float* __restrict__ beta)
{
    const float* act = src ? g_act2 : g_act1;
    const int f = blockIdx.x;
    const int t = threadIdx.x;

    float s = 0.f, s2 = 0.f;
    for (int idx = t; idx < B_ * L_; idx += 128) {
        int b = idx / L_;
        int l = idx - b * L_;
        float v = act[((size_t)b * F_ + f) * L_ + l];
        s += v; s2 += v * v;
    }
    __shared__ float rs[4], rs2[4];
#pragma unroll
    for (int o = 16; o > 0; o >>= 1) {
        s  += __shfl_down_sync(0xffffffffu, s, o);
        s2 += __shfl_down_sync(0xffffffffu, s2, o);
    }
    if ((t & 31) == 0) { rs[t >> 5] = s; rs2[t >> 5] = s2; }
    __syncthreads();
    if (t == 0) {
        float S  = rs[0] + rs[1] + rs[2] + rs[3];
        float S2 = rs2[0] + rs2[1] + rs2[2] + rs2[3];
        const float inv_n = 1.f / (float)(B_ * L_);
        float mean = S * inv_n;
        float var  = S2 * inv_n - mean * mean;
        float a = gamma[f] * rsqrtf(var + 1e-5f);
        g_aff[layer][f]      = a;
        g_aff[layer][F_ + f] = beta[f] - mean * a;
    }
}

// =================================================================================
// hb (unchanged)
// =================================================================================
__global__ void __launch_bounds__(128) hb_kernel(
    const float* __restrict__ h, const float* __restrict__ W1,
    const float* __restrict__ b1)
{
    const int b = blockIdx.x;
    const int n = threadIdx.x;
    __shared__ float h_s[E_];
    for (int k = n; k < E_; k += 128) h_s[k] = h[(size_t)b * E_ + k];
    __syncthreads();
    const float* Wc = W1 + (size_t)(2 * D_) * M_;
    float acc = b1[n];
#pragma unroll 4
    for (int k = 0; k < E_; k++) acc += h_s[k] * Wc[(size_t)k * M_ + n];
    g_hb[b * M_ + n] = acc;
}

// =================================================================================
// A / C projections (unchanged)
// =================================================================================
constexpr int LT = 20;

__global__ void __launch_bounds__(256) ac_kernel(const float* __restrict__ W1)
{
    const int b  = blockIdx.x;
    const int l0 = blockIdx.y * LT;
    const int t  = threadIdx.x;

    __shared__ float xf[LT][D_];

    const float* aff_a = g_aff[3];
    const float* aff_b = g_aff[3] + F_;

    for (int c = t; c < LT * D_; c += 256) {
        int ch = c / LT;
        int ll = c - ch * LT;
        int l  = l0 + ll;
        float v;
        if (ch < F_) {
            v = aff_a[ch] * g_act2[((size_t)b * F_ + ch) * L_ + l] + aff_b[ch];
        } else if (ch == F_) {
            v = ((float)l / 10.0f - 2.0f) * 0.5f;
        } else {
            v = ((float)(l % 10) - 2.0f) * 0.5f;
        }
        xf[ll][ch] = v;
    }
    __syncthreads();

    const int n  = t & 127;
    const int lg = t >> 7;

    float accA[LT / 2], accC[LT / 2];
#pragma unroll
    for (int i = 0; i < LT / 2; i++) { accA[i] = 0.f; accC[i] = 0.f; }

    const float* Wa = W1;
    const float* Wb = W1 + (size_t)D_ * M_;
#pragma unroll 2
    for (int c = 0; c < D_; c++) {
        float wa = Wa[(size_t)c * M_ + n];
        float wb = Wb[(size_t)c * M_ + n];
#pragma unroll
        for (int i = 0; i < LT / 2; i++) {
            float x = xf[2 * i + lg][c];
            accA[i] += x * wa;
            accC[i] += x * wb;
        }
    }
    float hbv = g_hb[b * M_ + n];
#pragma unroll
    for (int i = 0; i < LT / 2; i++) {
        int l = l0 + 2 * i + lg;
        g_A[((size_t)b * L_ + l) * M_ + n] = accA[i];
        g_C[((size_t)b * L_ + l) * M_ + n] = accC[i] + hbv;
    }
}

// =================================================================================
// Pack W2/W3/W4 transposed into bf16 hi/lo:  g_wpackT[layer][hl][n*128+k] = W[k][n]
// =================================================================================
__global__ void __launch_bounds__(256) pack_weights(
    const float* __restrict__ W2, const float* __restrict__ W3,
    const float* __restrict__ W4)
{
    for (int idx = blockIdx.x * 256 + threadIdx.x; idx < 3 * 128 * 128;
         idx += gridDim.x * 256) {
        int layer = idx / 16384;
        int rem   = idx - layer * 16384;
        int n = rem >> 7;
        int k = rem & 127;
        const float* W = layer == 0 ? W2 : (layer == 1 ? W3 : W4);
        float w = W[(size_t)k * 128 + n];
        __nv_bfloat16 hi = __float2bfloat16(w);
        float resid = w - __bfloat162float(hi);
        __nv_bfloat16 lo = __float2bfloat16(resid);
        g_wpackT[layer][0][n * 128 + k] = __bfloat16_as_ushort(hi);
        g_wpackT[layer][1][n * 128 + k] = __bfloat16_as_ushort(lo);
    }
}

// =================================================================================
// Tensor-core (mma.sync bf16 split) pairwise relation kernel — R4 version.
// =================================================================================
constexpr int WPITCH = 68;                  // 32-bit words per n-row (136 bf16)
constexpr int WLO    = 128 * WPITCH;        // word offset of lo weights
constexpr int SMEM_PW = 2 * 128 * WPITCH * 4;  // 69,632 B

DEV_INLINE void stageW(uint4* smW, int layer, int tid) {
    const uint4* src = (const uint4*)g_wpackT[layer];  // 4096 uint4
#pragma unroll
    for (int it = 0; it < 16; it++) {
        int idx = it * 256 + tid;
        int n2 = idx >> 4;       // hl*128 + n
        int kq = idx & 15;       // uint4 index along k
        smW[n2 * 17 + kq] = src[idx];
    }
}

__global__ void __launch_bounds__(256) pairwise_mma(
    const float* __restrict__ b2, const float* __restrict__ b3,
    const float* __restrict__ b4)
{
    extern __shared__ char smraw[];
    uint4*    smW  = (uint4*)smraw;
    uint32_t* smWw = (uint32_t*)smraw;
    float*    s_part = (float*)smraw;   // reused after final sync

    const int tile = blockIdx.x;
    const int b    = blockIdx.y;
    const int row0 = tile * 128;
    const int tid  = threadIdx.x;
    const int w    = tid >> 5;
    const int lane = tid & 31;
    const int g    = lane >> 2;
    const int t    = lane & 3;

    // ---- build layer-1 A fragments from global: g1 = lrelu(C_i + A_j) ----
    uint32_t Ah[8][4], Al[8][4];
    const int r0 = row0 + 16 * w + g;
    const int r1 = r0 + 8;
    {
        int rc0 = r0 < NPAIR ? r0 : 0;
        int rc1 = r1 < NPAIR ? r1 : 0;
        int i0 = rc0 / 100, j0 = rc0 - (rc0 / 100) * 100;
        int i1 = rc1 / 100, j1 = rc1 - (rc1 / 100) * 100;
        const float2* C0 = (const float2*)(g_C + ((size_t)b * L_ + i0) * M_);
        const float2* A0 = (const float2*)(g_A + ((size_t)b * L_ + j0) * M_);
        const float2* C1 = (const float2*)(g_C + ((size_t)b * L_ + i1) * M_);
        const float2* A1 = (const float2*)(g_A + ((size_t)b * L_ + j1) * M_);
#pragma unroll
        for (int c = 0; c < 8; c++) {
            int idx = 8 * c + t;
            float2 cc, aa;
            cc = C0[idx];     aa = A0[idx];
            split_pack2(lrelu(cc.x + aa.x), lrelu(cc.y + aa.y), Ah[c][0], Al[c][0]);
            cc = C1[idx];     aa = A1[idx];
            split_pack2(lrelu(cc.x + aa.x), lrelu(cc.y + aa.y), Ah[c][1], Al[c][1]);
            cc = C0[idx + 4]; aa = A0[idx + 4];
            split_pack2(lrelu(cc.x + aa.x), lrelu(cc.y + aa.y), Ah[c][2], Al[c][2]);
            cc = C1[idx + 4]; aa = A1[idx + 4];
            split_pack2(lrelu(cc.x + aa.x), lrelu(cc.y + aa.y), Ah[c][3], Al[c][3]);
        }
    }

    stageW(smW, 0, tid);
    __syncthreads();

#pragma unroll
    for (int layer = 0; layer < 3; layer++) {
        float acc[16][4];
#pragma unroll
        for (int nt = 0; nt < 16; nt++)
#pragma unroll
            for (int q = 0; q < 4; q++) acc[nt][q] = 0.f;

#pragma unroll
        for (int c = 0; c < 8; c++) {
#pragma unroll
            for (int nt = 0; nt < 16; nt++) {
                int wb = (nt * 8 + g) * WPITCH + 8 * c + t;
                uint32_t bh0 = smWw[wb];
                uint32_t bh1 = smWw[wb + 4];
                uint32_t bl0 = smWw[WLO + wb];
                uint32_t bl1 = smWw[WLO + wb + 4];
                mma16816(acc[nt], Ah[c], bh0, bh1);
                mma16816(acc[nt], Ah[c], bl0, bl1);
                mma16816(acc[nt], Al[c], bh0, bh1);
            }
        }

        if (layer < 2) {
            const float* bias = layer == 0 ? b2 : b3;
#pragma unroll
            for (int nt = 0; nt < 16; nt++) {
                int col = nt * 8 + 2 * t;
                float bb0 = __ldg(bias + col);
                float bb1 = __ldg(bias + col + 1);
                float z0 = lrelu(acc[nt][0] + bb0);
                float z1 = lrelu(acc[nt][1] + bb1);
                float z2 = lrelu(acc[nt][2] + bb0);
                float z3 = lrelu(acc[nt][3] + bb1);
                uint32_t hi01, lo01, hi23, lo23;
                split_pack2(z0, z1, hi01, lo01);
                split_pack2(z2, z3, hi23, lo23);
                int c2  = nt >> 1;
                int off = (nt & 1) * 2;
                Ah[c2][off]     = hi01;
                Ah[c2][off + 1] = hi23;
                Al[c2][off]     = lo01;
                Al[c2][off + 1] = lo23;
            }
            __syncthreads();              // everyone done reading W[layer]
            stageW(smW, layer + 1, tid);
            __syncthreads();
        } else {
            __syncthreads();              // done reading W3; smem now partials
            const bool live0 = r0 < NPAIR;
            const bool live1 = r1 < NPAIR;
#pragma unroll
            for (int nt = 0; nt < 16; nt++) {
                int col = nt * 8 + 2 * t;
                float bb0 = __ldg(b4 + col);
                float bb1 = __ldg(b4 + col + 1);
                float z0 = live0 ? lrelu(acc[nt][0] + bb0) : 0.f;
                float z1 = live0 ? lrelu(acc[nt][1] + bb1) : 0.f;
                float z2 = live1 ? lrelu(acc[nt][2] + bb0) : 0.f;
                float z3 = live1 ? lrelu(acc[nt][3] + bb1) : 0.f;
                float v0 = z0 + z2;
                float v1 = z1 + z3;
#pragma unroll
                for (int o = 4; o < 32; o <<= 1) {
                    v0 += __shfl_xor_sync(0xffffffffu, v0, o);
                    v1 += __shfl_xor_sync(0xffffffffu, v1, o);
                }
                if (g == 0) {
                    s_part[w * 128 + col]     = v0;
                    s_part[w * 128 + col + 1] = v1;
                }
            }
            __syncthreads();
            if (tid < 128) {
                float ss = 0.f;
#pragma unroll
                for (int ww = 0; ww < 8; ww++) ss += s_part[ww * 128 + tid];
                g_part[((size_t)b * NTILE + tile) * M_ + tid] = ss;
            }
        }
    }
}

// =================================================================================
// Final decoder (unchanged)
// =================================================================================
__global__ void __launch_bounds__(128) final_kernel(
    const float* __restrict__ F1, const float* __restrict__ fb1,
    const float* __restrict__ F2, const float* __restrict__ fb2,
    float* __restrict__ out)
{
    const int b = blockIdx.x;
    const int t = threadIdx.x;
    __shared__ float s_s[M_], t_s[M_];

    float acc = 0.f;
    for (int i = 0; i < NTILE; i++)
        acc += g_part[((size_t)b * NTILE + i) * M_ + t];
    s_s[t] = acc;
    __syncthreads();

    float a2 = fb1[t];
#pragma unroll 4
    for (int k = 0; k < M_; k++) a2 += s_s[k] * F1[(size_t)k * M_ + t];
    t_s[t] = lrelu(a2);
    __syncthreads();

    for (int m = t; m < 512; m += 128) {
        float a3 = fb2[m];
#pragma unroll 4
        for (int k = 0; k < M_; k++) a3 += t_s[k] * F2[(size_t)k * 512 + m];
        out[(size_t)b * 512 + m] = lrelu(a3);
    }
}

// =================================================================================
// launcher
// =================================================================================
extern "C" void kernel_launch(void* const* d_in, const int* in_sizes, int n_in,
                              void* d_out, int out_size)
{
    (void)in_sizes; (void)n_in; (void)out_size;

    const float* x   = (const float*)d_in[0];
    const float* h   = (const float*)d_in[1];
    const float* cw1 = (const float*)d_in[2];
    const float* cb1 = (const float*)d_in[3];
    const float* ga1 = (const float*)d_in[4];
    const float* be1 = (const float*)d_in[5];
    const float* cw2 = (const float*)d_in[6];
    const float* cb2 = (const float*)d_in[7];
    const float* ga2 = (const float*)d_in[8];
    const float* be2 = (const float*)d_in[9];
    const float* cw3 = (const float*)d_in[10];
    const float* cb3 = (const float*)d_in[11];
    const float* ga3 = (const float*)d_in[12];
    const float* be3 = (const float*)d_in[13];
    const float* cw4 = (const float*)d_in[14];
    const float* cb4 = (const float*)d_in[15];
    const float* ga4 = (const float*)d_in[16];
    const float* be4 = (const float*)d_in[17];
    const float* W1  = (const float*)d_in[18];
    const float* b1  = (const float*)d_in[19];
    const float* W2  = (const float*)d_in[20];
    const float* b2  = (const float*)d_in[21];
    const float* W3  = (const float*)d_in[22];
    const float* b3  = (const float*)d_in[23];
    const float* W4  = (const float*)d_in[24];
    const float* b4  = (const float*)d_in[25];
    const float* F1  = (const float*)d_in[26];
    const float* fb1 = (const float*)d_in[27];
    const float* F2  = (const float*)d_in[28];
    const float* fb2 = (const float*)d_in[29];
    float* out = (float*)d_out;

    // weight packing first (reads inputs only)
    pack_convw<<<192, 256>>>(cw1, cw2, cw3, cw4);
    pack_weights<<<96, 256>>>(W2, W3, W4);

    dim3 cgrid(B_, F_ / 16);

    // conv / BN stack (register-tiled conv v2; weight pointer resolved on device)
    conv2_kernel<E_, true ><<<cgrid, 64>>>(x, 0, 0, /*wsel=*/-1, cb1, 0);
    stats_kernel<<<F_, 128>>>(0, 0, ga1, be1);
    conv2_kernel<F_, false><<<cgrid, 64>>>(nullptr, 0, 0, /*wsel=*/0, cb2, 1);
    stats_kernel<<<F_, 128>>>(1, 1, ga2, be2);
    conv2_kernel<F_, false><<<cgrid, 64>>>(nullptr, 1, 1, /*wsel=*/1, cb3, 0);
    stats_kernel<<<F_, 128>>>(0, 2, ga3, be3);
    conv2_kernel<F_, false><<<cgrid, 64>>>(nullptr, 0, 2, /*wsel=*/2, cb4, 1);
    stats_kernel<<<F_, 128>>>(1, 3, ga4, be4);

    // projections
    hb_kernel<<<B_, 128>>>(h, W1, b1);
    ac_kernel<<<dim3(B_, L_ / LT), 256>>>(W1);

    // tensor-core pairwise chain (R4 version, proven)
    cudaFuncSetAttribute(pairwise_mma,
                         cudaFuncAttributeMaxDynamicSharedMemorySize, SMEM_PW);
    pairwise_mma<<<dim3(NTILE, B_), 256, SMEM_PW>>>(b2, b3, b4);

    // decoder
    final_kernel<<<B_, 128>>>(F1, fb1, F2, fb2, out);
}

// round 8
// speedup vs baseline: 1.3127x; 1.3127x over previous
#include <cuda_runtime.h>
#include <cuda_bf16.h>
#include <cstdint>

#define DEV_INLINE __device__ __forceinline__

constexpr int L_   = 100;
constexpr int B_   = 32;
constexpr int E_   = 512;
constexpr int F_   = 256;
constexpr int M_   = 128;
constexpr int D_   = 258;
constexpr int NPAIR = L_ * L_;                 // 10000
constexpr int NTILE = (NPAIR + 127) / 128;     // 79

// ---------------- scratch (device globals; no allocation allowed) ----------------
__device__ float g_act1[B_ * F_ * L_];
__device__ float g_act2[B_ * F_ * L_];
__device__ float g_aff[4][2 * F_];             // per layer: [a (F)], [b (F)]
__device__ float g_A[B_ * L_ * M_];
__device__ float g_C[B_ * L_ * M_];
__device__ float g_hb[B_ * M_];
__device__ float g_part[B_ * NTILE * M_];
// fragment-packed weights: [layer][n*32 + slot] = {bh0, bh1, bl0, bl1}
// slot = (c*4+t) ^ ((n&1)*4)  (bank-conflict-free LDS.128)
__device__ __align__(16) uint4 g_wpack2[3][128 * 32];

DEV_INLINE float lrelu(float z) { return fmaxf(z, 0.f) + 0.1f * fminf(z, 0.f); }

DEV_INLINE void split_pack2(float x0, float x1, uint32_t& hi, uint32_t& lo) {
    __nv_bfloat16 h0 = __float2bfloat16(x0);
    __nv_bfloat16 h1 = __float2bfloat16(x1);
    float r0 = x0 - __bfloat162float(h0);
    float r1 = x1 - __bfloat162float(h1);
    __nv_bfloat16 l0 = __float2bfloat16(r0);
    __nv_bfloat16 l1 = __float2bfloat16(r1);
    hi = ((uint32_t)__bfloat16_as_ushort(h1) << 16) | (uint32_t)__bfloat16_as_ushort(h0);
    lo = ((uint32_t)__bfloat16_as_ushort(l1) << 16) | (uint32_t)__bfloat16_as_ushort(l0);
}

DEV_INLINE uint32_t pack_bf16_pair(float x0, float x1) {
    __nv_bfloat16 h0 = __float2bfloat16(x0);
    __nv_bfloat16 h1 = __float2bfloat16(x1);
    return ((uint32_t)__bfloat16_as_ushort(h1) << 16) | (uint32_t)__bfloat16_as_ushort(h0);
}

DEV_INLINE void mma16816(float c[4], const uint32_t a[4], uint32_t b0, uint32_t b1) {
    asm volatile(
        "mma.sync.aligned.m16n8k16.row.col.f32.bf16.bf16.f32 "
        "{%0,%1,%2,%3}, {%4,%5,%6,%7}, {%8,%9}, {%0,%1,%2,%3};"
        : "+f"(c[0]), "+f"(c[1]), "+f"(c[2]), "+f"(c[3])
        : "r"(a[0]), "r"(a[1]), "r"(a[2]), "r"(a[3]), "r"(b0), "r"(b1));
}

// =================================================================================
// Conv1d (K=3, pad 1) + bias + leakyReLU — R4 version (proven).
// =================================================================================
constexpr int EC = 32;
constexpr int FT = 16;

template <int EIN, bool FIRST>
__global__ void __launch_bounds__(128) conv_kernel(
    const float* __restrict__ in_ext, int src, int aff_layer,
    const float* __restrict__ w, const float* __restrict__ cb, int dst)
{
    __shared__ float in_s[EC][L_ + 2];
    __shared__ float w_s[EC][3][FT];

    const int b  = blockIdx.x;
    const int f0 = blockIdx.y * FT;
    const int t  = threadIdx.x;

    const float* in  = FIRST ? in_ext : (src ? g_act2 : g_act1);
    float*       out = dst ? g_act2 : g_act1;
    const float* aff_a = g_aff[aff_layer];
    const float* aff_b = g_aff[aff_layer] + F_;

    float acc[FT];
#pragma unroll
    for (int i = 0; i < FT; i++) acc[i] = 0.f;

    for (int e0 = 0; e0 < EIN; e0 += EC) {
        __syncthreads();
        for (int c = t; c < EC * (L_ + 2); c += 128) {
            int e, lo;
            if (FIRST) { e = c & (EC - 1); lo = c >> 5; }
            else       { e = c / (L_ + 2); lo = c - e * (L_ + 2); }
            int l = lo - 1;
            float v = 0.f;
            if (l >= 0 && l < L_) {
                if (FIRST) {
                    v = in[(size_t)l * (B_ * E_) + (size_t)b * E_ + (e0 + e)];
                } else {
                    v = in[((size_t)b * EIN + (e0 + e)) * L_ + l];
                    v = aff_a[e0 + e] * v + aff_b[e0 + e];
                }
            }
            in_s[e][lo] = v;
        }
        for (int c = t; c < EC * 3 * FT; c += 128) {
            int fl = c & (FT - 1);
            int rest = c >> 4;
            int k = rest % 3;
            int e = rest / 3;
            w_s[e][k][fl] = w[((size_t)(f0 + fl) * EIN + (e0 + e)) * 3 + k];
        }
        __syncthreads();

        if (t < L_) {
#pragma unroll 4
            for (int e = 0; e < EC; e++) {
                float x0 = in_s[e][t];
                float x1 = in_s[e][t + 1];
                float x2 = in_s[e][t + 2];
#pragma unroll
                for (int fl = 0; fl < FT; fl++) {
                    acc[fl] += x0 * w_s[e][0][fl];
                    acc[fl] += x1 * w_s[e][1][fl];
                    acc[fl] += x2 * w_s[e][2][fl];
                }
            }
        }
    }

    if (t < L_) {
#pragma unroll
        for (int fl = 0; fl < FT; fl++) {
            float z = acc[fl] + cb[f0 + fl];
            out[((size_t)b * F_ + (f0 + fl)) * L_ + t] = lrelu(z);
        }
    }
}

// =================================================================================
// BN stats (unchanged)
// =================================================================================
__global__ void __launch_bounds__(128) stats_kernel(
    int src, int layer,
    const float* __restrict__ gamma, const float* __restrict__ beta)
{
    const float* act = src ? g_act2 : g_act1;
    const int f = blockIdx.x;
    const int t = threadIdx.x;

    float s = 0.f, s2 = 0.f;
    for (int idx = t; idx < B_ * L_; idx += 128) {
        int b = idx / L_;
        int l = idx - b * L_;
        float v = act[((size_t)b * F_ + f) * L_ + l];
        s += v; s2 += v * v;
    }
    __shared__ float rs[4], rs2[4];
#pragma unroll
    for (int o = 16; o > 0; o >>= 1) {
        s  += __shfl_down_sync(0xffffffffu, s, o);
        s2 += __shfl_down_sync(0xffffffffu, s2, o);
    }
    if ((t & 31) == 0) { rs[t >> 5] = s; rs2[t >> 5] = s2; }
    __syncthreads();
    if (t == 0) {
        float S  = rs[0] + rs[1] + rs[2] + rs[3];
        float S2 = rs2[0] + rs2[1] + rs2[2] + rs2[3];
        const float inv_n = 1.f / (float)(B_ * L_);
        float mean = S * inv_n;
        float var  = S2 * inv_n - mean * mean;
        float a = gamma[f] * rsqrtf(var + 1e-5f);
        g_aff[layer][f]      = a;
        g_aff[layer][F_ + f] = beta[f] - mean * a;
    }
}

// =================================================================================
// hb (unchanged)
// =================================================================================
__global__ void __launch_bounds__(128) hb_kernel(
    const float* __restrict__ h, const float* __restrict__ W1,
    const float* __restrict__ b1)
{
    const int b = blockIdx.x;
    const int n = threadIdx.x;
    __shared__ float h_s[E_];
    for (int k = n; k < E_; k += 128) h_s[k] = h[(size_t)b * E_ + k];
    __syncthreads();
    const float* Wc = W1 + (size_t)(2 * D_) * M_;
    float acc = b1[n];
#pragma unroll 4
    for (int k = 0; k < E_; k++) acc += h_s[k] * Wc[(size_t)k * M_ + n];
    g_hb[b * M_ + n] = acc;
}

// =================================================================================
// A / C projections (unchanged)
// =================================================================================
constexpr int LT = 20;

__global__ void __launch_bounds__(256) ac_kernel(const float* __restrict__ W1)
{
    const int b  = blockIdx.x;
    const int l0 = blockIdx.y * LT;
    const int t  = threadIdx.x;

    __shared__ float xf[LT][D_];

    const float* aff_a = g_aff[3];
    const float* aff_b = g_aff[3] + F_;

    for (int c = t; c < LT * D_; c += 256) {
        int ch = c / LT;
        int ll = c - ch * LT;
        int l  = l0 + ll;
        float v;
        if (ch < F_) {
            v = aff_a[ch] * g_act2[((size_t)b * F_ + ch) * L_ + l] + aff_b[ch];
        } else if (ch == F_) {
            v = ((float)l / 10.0f - 2.0f) * 0.5f;
        } else {
            v = ((float)(l % 10) - 2.0f) * 0.5f;
        }
        xf[ll][ch] = v;
    }
    __syncthreads();

    const int n  = t & 127;
    const int lg = t >> 7;

    float accA[LT / 2], accC[LT / 2];
#pragma unroll
    for (int i = 0; i < LT / 2; i++) { accA[i] = 0.f; accC[i] = 0.f; }

    const float* Wa = W1;
    const float* Wb = W1 + (size_t)D_ * M_;
#pragma unroll 2
    for (int c = 0; c < D_; c++) {
        float wa = Wa[(size_t)c * M_ + n];
        float wb = Wb[(size_t)c * M_ + n];
#pragma unroll
        for (int i = 0; i < LT / 2; i++) {
            float x = xf[2 * i + lg][c];
            accA[i] += x * wa;
            accC[i] += x * wb;
        }
    }
    float hbv = g_hb[b * M_ + n];
#pragma unroll
    for (int i = 0; i < LT / 2; i++) {
        int l = l0 + 2 * i + lg;
        g_A[((size_t)b * L_ + l) * M_ + n] = accA[i];
        g_C[((size_t)b * L_ + l) * M_ + n] = accC[i] + hbv;
    }
}

// =================================================================================
// Pack W2/W3/W4 into fragment-ready uint4s:
//   g_wpack2[layer][n*32 + slot] = {hi(kw=8c+t), hi(8c+4+t), lo(8c+t), lo(8c+4+t)}
//   slot = (c*4+t) ^ ((n&1)*4)
// where word kw covers weights k = 2kw, 2kw+1 of column n.
// =================================================================================
__global__ void __launch_bounds__(256) pack_weights(
    const float* __restrict__ W2, const float* __restrict__ W3,
    const float* __restrict__ W4)
{
    int idx = blockIdx.x * 256 + threadIdx.x;       // 0 .. 12287
    if (idx >= 3 * 128 * 32) return;
    int layer = idx >> 12;
    int rem   = idx & 4095;
    int n = rem >> 5;
    int s = rem & 31;
    int c = s >> 2;
    int t = s & 3;
    const float* W = layer == 0 ? W2 : (layer == 1 ? W3 : W4);

    uint32_t hw[2], lw[2];
#pragma unroll
    for (int j = 0; j < 2; j++) {
        int kw = 8 * c + 4 * j + t;
        float w0 = W[(size_t)(2 * kw) * 128 + n];
        float w1 = W[(size_t)(2 * kw + 1) * 128 + n];
        split_pack2(w0, w1, hw[j], lw[j]);
    }
    int slot = (c * 4 + t) ^ ((n & 1) * 4);
    g_wpack2[layer][n * 32 + slot] = make_uint4(hw[0], hw[1], lw[0], lw[1]);
}

// =================================================================================
// Tensor-core pairwise relation kernel (R4 structure, fragment-packed weights).
// Per inner group: ONE LDS.128 feeds all 3 split-term MMAs.
// =================================================================================
constexpr int SMEM_PW = 128 * 32 * 16;   // 65,536 B

DEV_INLINE void stageW(uint4* smW, int layer, int tid) {
    const uint4* src = g_wpack2[layer];   // 4096 uint4, linear
#pragma unroll
    for (int it = 0; it < 16; it++)
        smW[it * 256 + tid] = src[it * 256 + tid];
}

__global__ void __launch_bounds__(256) pairwise_mma(
    const float* __restrict__ b2, const float* __restrict__ b3,
    const float* __restrict__ b4)
{
    extern __shared__ char smraw[];
    uint4* smW    = (uint4*)smraw;
    float* s_part = (float*)smraw;      // reused after final sync

    const int tile = blockIdx.x;
    const int b    = blockIdx.y;
    const int row0 = tile * 128;
    const int tid  = threadIdx.x;
    const int w    = tid >> 5;
    const int lane = tid & 31;
    const int g    = lane >> 2;
    const int t    = lane & 3;

    // ---- build layer-1 A fragments from global: g1 = lrelu(C_i + A_j) ----
    uint32_t Ah[8][4], Al[8][4];
    const int r0 = row0 + 16 * w + g;
    const int r1 = r0 + 8;
    {
        int rc0 = r0 < NPAIR ? r0 : 0;
        int rc1 = r1 < NPAIR ? r1 : 0;
        int i0 = rc0 / 100, j0 = rc0 - (rc0 / 100) * 100;
        int i1 = rc1 / 100, j1 = rc1 - (rc1 / 100) * 100;
        const float2* C0 = (const float2*)(g_C + ((size_t)b * L_ + i0) * M_);
        const float2* A0 = (const float2*)(g_A + ((size_t)b * L_ + j0) * M_);
        const float2* C1 = (const float2*)(g_C + ((size_t)b * L_ + i1) * M_);
        const float2* A1 = (const float2*)(g_A + ((size_t)b * L_ + j1) * M_);
#pragma unroll
        for (int c = 0; c < 8; c++) {
            int idx = 8 * c + t;
            float2 cc, aa;
            cc = C0[idx];     aa = A0[idx];
            split_pack2(lrelu(cc.x + aa.x), lrelu(cc.y + aa.y), Ah[c][0], Al[c][0]);
            cc = C1[idx];     aa = A1[idx];
            split_pack2(lrelu(cc.x + aa.x), lrelu(cc.y + aa.y), Ah[c][1], Al[c][1]);
            cc = C0[idx + 4]; aa = A0[idx + 4];
            split_pack2(lrelu(cc.x + aa.x), lrelu(cc.y + aa.y), Ah[c][2], Al[c][2]);
            cc = C1[idx + 4]; aa = A1[idx + 4];
            split_pack2(lrelu(cc.x + aa.x), lrelu(cc.y + aa.y), Ah[c][3], Al[c][3]);
        }
    }

    stageW(smW, 0, tid);
    __syncthreads();

#pragma unroll
    for (int layer = 0; layer < 3; layer++) {
        float acc[16][4];
#pragma unroll
        for (int nt = 0; nt < 16; nt++)
#pragma unroll
            for (int q = 0; q < 4; q++) acc[nt][q] = 0.f;

#pragma unroll
        for (int c = 0; c < 8; c++) {
            const int base_slot = c * 4 + t;
#pragma unroll
            for (int nt = 0; nt < 16; nt++) {
                const int n = nt * 8 + g;
                uint4 f4 = smW[n * 32 + (base_slot ^ ((n & 1) * 4))];
                mma16816(acc[nt], Ah[c], f4.x, f4.y);
                mma16816(acc[nt], Ah[c], f4.z, f4.w);
                mma16816(acc[nt], Al[c], f4.x, f4.y);
            }
        }

        if (layer < 2) {
            const float* bias = layer == 0 ? b2 : b3;
#pragma unroll
            for (int nt = 0; nt < 16; nt++) {
                int col = nt * 8 + 2 * t;
                float bb0 = __ldg(bias + col);
                float bb1 = __ldg(bias + col + 1);
                float z0 = lrelu(acc[nt][0] + bb0);
                float z1 = lrelu(acc[nt][1] + bb1);
                float z2 = lrelu(acc[nt][2] + bb0);
                float z3 = lrelu(acc[nt][3] + bb1);
                uint32_t hi01, lo01, hi23, lo23;
                split_pack2(z0, z1, hi01, lo01);
                split_pack2(z2, z3, hi23, lo23);
                int c2  = nt >> 1;
                int off = (nt & 1) * 2;
                Ah[c2][off]     = hi01;
                Ah[c2][off + 1] = hi23;
                Al[c2][off]     = lo01;
                Al[c2][off + 1] = lo23;
            }
            __syncthreads();              // everyone done reading W[layer]
            stageW(smW, layer + 1, tid);
            __syncthreads();
        } else {
            __syncthreads();              // done reading W3; smem now partials
            const bool live0 = r0 < NPAIR;
            const bool live1 = r1 < NPAIR;
#pragma unroll
            for (int nt = 0; nt < 16; nt++) {
                int col = nt * 8 + 2 * t;
                float bb0 = __ldg(b4 + col);
                float bb1 = __ldg(b4 + col + 1);
                float z0 = live0 ? lrelu(acc[nt][0] + bb0) : 0.f;
                float z1 = live0 ? lrelu(acc[nt][1] + bb1) : 0.f;
                float z2 = live1 ? lrelu(acc[nt][2] + bb0) : 0.f;
                float z3 = live1 ? lrelu(acc[nt][3] + bb1) : 0.f;
                float v0 = z0 + z2;
                float v1 = z1 + z3;
#pragma unroll
                for (int o = 4; o < 32; o <<= 1) {
                    v0 += __shfl_xor_sync(0xffffffffu, v0, o);
                    v1 += __shfl_xor_sync(0xffffffffu, v1, o);
                }
                if (g == 0) {
                    s_part[w * 128 + col]     = v0;
                    s_part[w * 128 + col + 1] = v1;
                }
            }
            __syncthreads();
            if (tid < 128) {
                float ss = 0.f;
#pragma unroll
                for (int ww = 0; ww < 8; ww++) ss += s_part[ww * 128 + tid];
                g_part[((size_t)b * NTILE + tile) * M_ + tid] = ss;
            }
        }
    }
}

// =================================================================================
// Final decoder (unchanged)
// =================================================================================
__global__ void __launch_bounds__(128) final_kernel(
    const float* __restrict__ F1, const float* __restrict__ fb1,
    const float* __restrict__ F2, const float* __restrict__ fb2,
    float* __restrict__ out)
{
    const int b = blockIdx.x;
    const int t = threadIdx.x;
    __shared__ float s_s[M_], t_s[M_];

    float acc = 0.f;
    for (int i = 0; i < NTILE; i++)
        acc += g_part[((size_t)b * NTILE + i) * M_ + t];
    s_s[t] = acc;
    __syncthreads();

    float a2 = fb1[t];
#pragma unroll 4
    for (int k = 0; k < M_; k++) a2 += s_s[k] * F1[(size_t)k * M_ + t];
    t_s[t] = lrelu(a2);
    __syncthreads();

    for (int m = t; m < 512; m += 128) {
        float a3 = fb2[m];
#pragma unroll 4
        for (int k = 0; k < M_; k++) a3 += t_s[k] * F2[(size_t)k * 512 + m];
        out[(size_t)b * 512 + m] = lrelu(a3);
    }
}

// =================================================================================
// launcher
// =================================================================================
extern "C" void kernel_launch(void* const* d_in, const int* in_sizes, int n_in,
                              void* d_out, int out_size)
{
    (void)in_sizes; (void)n_in; (void)out_size;

    const float* x   = (const float*)d_in[0];
    const float* h   = (const float*)d_in[1];
    const float* cw1 = (const float*)d_in[2];
    const float* cb1 = (const float*)d_in[3];
    const float* ga1 = (const float*)d_in[4];
    const float* be1 = (const float*)d_in[5];
    const float* cw2 = (const float*)d_in[6];
    const float* cb2 = (const float*)d_in[7];
    const float* ga2 = (const float*)d_in[8];
    const float* be2 = (const float*)d_in[9];
    const float* cw3 = (const float*)d_in[10];
    const float* cb3 = (const float*)d_in[11];
    const float* ga3 = (const float*)d_in[12];
    const float* be3 = (const float*)d_in[13];
    const float* cw4 = (const float*)d_in[14];
    const float* cb4 = (const float*)d_in[15];
    const float* ga4 = (const float*)d_in[16];
    const float* be4 = (const float*)d_in[17];
    const float* W1  = (const float*)d_in[18];
    const float* b1  = (const float*)d_in[19];
    const float* W2  = (const float*)d_in[20];
    const float* b2  = (const float*)d_in[21];
    const float* W3  = (const float*)d_in[22];
    const float* b3  = (const float*)d_in[23];
    const float* W4  = (const float*)d_in[24];
    const float* b4  = (const float*)d_in[25];
    const float* F1  = (const float*)d_in[26];
    const float* fb1 = (const float*)d_in[27];
    const float* F2  = (const float*)d_in[28];
    const float* fb2 = (const float*)d_in[29];
    float* out = (float*)d_out;

    dim3 cgrid(B_, F_ / FT);

    // conv / BN stack (R4 conv, proven)
    conv_kernel<E_, true ><<<cgrid, 128>>>(x, 0, 0, cw1, cb1, 0);
    stats_kernel<<<F_, 128>>>(0, 0, ga1, be1);
    conv_kernel<F_, false><<<cgrid, 128>>>(nullptr, 0, 0, cw2, cb2, 1);
    stats_kernel<<<F_, 128>>>(1, 1, ga2, be2);
    conv_kernel<F_, false><<<cgrid, 128>>>(nullptr, 1, 1, cw3, cb3, 0);
    stats_kernel<<<F_, 128>>>(0, 2, ga3, be3);
    conv_kernel<F_, false><<<cgrid, 128>>>(nullptr, 0, 2, cw4, cb4, 1);
    stats_kernel<<<F_, 128>>>(1, 3, ga4, be4);

    // fragment-packed weight prep
    pack_weights<<<48, 256>>>(W2, W3, W4);

    // projections
    hb_kernel<<<B_, 128>>>(h, W1, b1);
    ac_kernel<<<dim3(B_, L_ / LT), 256>>>(W1);

    // tensor-core pairwise chain (single-LDS.128 fragment loads)
    cudaFuncSetAttribute(pairwise_mma,
                         cudaFuncAttributeMaxDynamicSharedMemorySize, SMEM_PW);
    pairwise_mma<<<dim3(NTILE, B_), 256, SMEM_PW>>>(b2, b3, b4);

    // decoder
    final_kernel<<<B_, 128>>>(F1, fb1, F2, fb2, out);
}

// round 9
// speedup vs baseline: 1.3955x; 1.0631x over previous
#include <cuda_runtime.h>
#include <cuda_bf16.h>
#include <cuda_fp16.h>
#include <cstdint>

#define DEV_INLINE __device__ __forceinline__

constexpr int L_   = 100;
constexpr int B_   = 32;
constexpr int E_   = 512;
constexpr int F_   = 256;
constexpr int M_   = 128;
constexpr int D_   = 258;
constexpr int NPAIR = L_ * L_;                 // 10000
constexpr int NTILE = (NPAIR + 127) / 128;     // 79

// ---------------- scratch (device globals; no allocation allowed) ----------------
__device__ float g_act1[B_ * F_ * L_];
__device__ float g_act2[B_ * F_ * L_];
__device__ float g_aff[4][2 * F_];             // per layer: [a (F)], [b (F)]
__device__ float g_A[B_ * L_ * M_];
__device__ float g_C[B_ * L_ * M_];
__device__ float g_hb[B_ * M_];
__device__ float g_part[B_ * NTILE * M_];
// fragment-packed fp16 weights: [layer][n*32 + slot] = {wh0, wh1, wl0, wl1}
// slot = (c*4+t) ^ ((n&1)*4)  (bank-conflict-free LDS.128)
__device__ __align__(16) uint4 g_wpack2[3][128 * 32];

DEV_INLINE float lrelu(float z) { return fmaxf(z, 0.f) + 0.1f * fminf(z, 0.f); }

DEV_INLINE uint32_t pack_h2(float x0, float x1) {
    __half2 h = __floats2half2_rn(x0, x1);
    return *reinterpret_cast<uint32_t*>(&h);
}

DEV_INLINE void mma16816_f16(float c[4], const uint32_t a[4], uint32_t b0, uint32_t b1) {
    asm volatile(
        "mma.sync.aligned.m16n8k16.row.col.f32.f16.f16.f32 "
        "{%0,%1,%2,%3}, {%4,%5,%6,%7}, {%8,%9}, {%0,%1,%2,%3};"
        : "+f"(c[0]), "+f"(c[1]), "+f"(c[2]), "+f"(c[3])
        : "r"(a[0]), "r"(a[1]), "r"(a[2]), "r"(a[3]), "r"(b0), "r"(b1));
}

// =================================================================================
// Conv1d (K=3, pad 1) + bias + leakyReLU — R4 version (proven).
// =================================================================================
constexpr int EC = 32;
constexpr int FT = 16;

template <int EIN, bool FIRST>
__global__ void __launch_bounds__(128) conv_kernel(
    const float* __restrict__ in_ext, int src, int aff_layer,
    const float* __restrict__ w, const float* __restrict__ cb, int dst)
{
    __shared__ float in_s[EC][L_ + 2];
    __shared__ float w_s[EC][3][FT];

    const int b  = blockIdx.x;
    const int f0 = blockIdx.y * FT;
    const int t  = threadIdx.x;

    const float* in  = FIRST ? in_ext : (src ? g_act2 : g_act1);
    float*       out = dst ? g_act2 : g_act1;
    const float* aff_a = g_aff[aff_layer];
    const float* aff_b = g_aff[aff_layer] + F_;

    float acc[FT];
#pragma unroll
    for (int i = 0; i < FT; i++) acc[i] = 0.f;

    for (int e0 = 0; e0 < EIN; e0 += EC) {
        __syncthreads();
        for (int c = t; c < EC * (L_ + 2); c += 128) {
            int e, lo;
            if (FIRST) { e = c & (EC - 1); lo = c >> 5; }
            else       { e = c / (L_ + 2); lo = c - e * (L_ + 2); }
            int l = lo - 1;
            float v = 0.f;
            if (l >= 0 && l < L_) {
                if (FIRST) {
                    v = in[(size_t)l * (B_ * E_) + (size_t)b * E_ + (e0 + e)];
                } else {
                    v = in[((size_t)b * EIN + (e0 + e)) * L_ + l];
                    v = aff_a[e0 + e] * v + aff_b[e0 + e];
                }
            }
            in_s[e][lo] = v;
        }
        for (int c = t; c < EC * 3 * FT; c += 128) {
            int fl = c & (FT - 1);
            int rest = c >> 4;
            int k = rest % 3;
            int e = rest / 3;
            w_s[e][k][fl] = w[((size_t)(f0 + fl) * EIN + (e0 + e)) * 3 + k];
        }
        __syncthreads();

        if (t < L_) {
#pragma unroll 4
            for (int e = 0; e < EC; e++) {
                float x0 = in_s[e][t];
                float x1 = in_s[e][t + 1];
                float x2 = in_s[e][t + 2];
#pragma unroll
                for (int fl = 0; fl < FT; fl++) {
                    acc[fl] += x0 * w_s[e][0][fl];
                    acc[fl] += x1 * w_s[e][1][fl];
                    acc[fl] += x2 * w_s[e][2][fl];
                }
            }
        }
    }

    if (t < L_) {
#pragma unroll
        for (int fl = 0; fl < FT; fl++) {
            float z = acc[fl] + cb[f0 + fl];
            out[((size_t)b * F_ + (f0 + fl)) * L_ + t] = lrelu(z);
        }
    }
}

// =================================================================================
// BN stats (unchanged)
// =================================================================================
__global__ void __launch_bounds__(128) stats_kernel(
    int src, int layer,
    const float* __restrict__ gamma, const float* __restrict__ beta)
{
    const float* act = src ? g_act2 : g_act1;
    const int f = blockIdx.x;
    const int t = threadIdx.x;

    float s = 0.f, s2 = 0.f;
    for (int idx = t; idx < B_ * L_; idx += 128) {
        int b = idx / L_;
        int l = idx - b * L_;
        float v = act[((size_t)b * F_ + f) * L_ + l];
        s += v; s2 += v * v;
    }
    __shared__ float rs[4], rs2[4];
#pragma unroll
    for (int o = 16; o > 0; o >>= 1) {
        s  += __shfl_down_sync(0xffffffffu, s, o);
        s2 += __shfl_down_sync(0xffffffffu, s2, o);
    }
    if ((t & 31) == 0) { rs[t >> 5] = s; rs2[t >> 5] = s2; }
    __syncthreads();
    if (t == 0) {
        float S  = rs[0] + rs[1] + rs[2] + rs[3];
        float S2 = rs2[0] + rs2[1] + rs2[2] + rs2[3];
        const float inv_n = 1.f / (float)(B_ * L_);
        float mean = S * inv_n;
        float var  = S2 * inv_n - mean * mean;
        float a = gamma[f] * rsqrtf(var + 1e-5f);
        g_aff[layer][f]      = a;
        g_aff[layer][F_ + f] = beta[f] - mean * a;
    }
}

// =================================================================================
// hb (unchanged)
// =================================================================================
__global__ void __launch_bounds__(128) hb_kernel(
    const float* __restrict__ h, const float* __restrict__ W1,
    const float* __restrict__ b1)
{
    const int b = blockIdx.x;
    const int n = threadIdx.x;
    __shared__ float h_s[E_];
    for (int k = n; k < E_; k += 128) h_s[k] = h[(size_t)b * E_ + k];
    __syncthreads();
    const float* Wc = W1 + (size_t)(2 * D_) * M_;
    float acc = b1[n];
#pragma unroll 4
    for (int k = 0; k < E_; k++) acc += h_s[k] * Wc[(size_t)k * M_ + n];
    g_hb[b * M_ + n] = acc;
}

// =================================================================================
// A / C projections (unchanged)
// =================================================================================
constexpr int LT = 20;

__global__ void __launch_bounds__(256) ac_kernel(const float* __restrict__ W1)
{
    const int b  = blockIdx.x;
    const int l0 = blockIdx.y * LT;
    const int t  = threadIdx.x;

    __shared__ float xf[LT][D_];

    const float* aff_a = g_aff[3];
    const float* aff_b = g_aff[3] + F_;

    for (int c = t; c < LT * D_; c += 256) {
        int ch = c / LT;
        int ll = c - ch * LT;
        int l  = l0 + ll;
        float v;
        if (ch < F_) {
            v = aff_a[ch] * g_act2[((size_t)b * F_ + ch) * L_ + l] + aff_b[ch];
        } else if (ch == F_) {
            v = ((float)l / 10.0f - 2.0f) * 0.5f;
        } else {
            v = ((float)(l % 10) - 2.0f) * 0.5f;
        }
        xf[ll][ch] = v;
    }
    __syncthreads();

    const int n  = t & 127;
    const int lg = t >> 7;

    float accA[LT / 2], accC[LT / 2];
#pragma unroll
    for (int i = 0; i < LT / 2; i++) { accA[i] = 0.f; accC[i] = 0.f; }

    const float* Wa = W1;
    const float* Wb = W1 + (size_t)D_ * M_;
#pragma unroll 2
    for (int c = 0; c < D_; c++) {
        float wa = Wa[(size_t)c * M_ + n];
        float wb = Wb[(size_t)c * M_ + n];
#pragma unroll
        for (int i = 0; i < LT / 2; i++) {
            float x = xf[2 * i + lg][c];
            accA[i] += x * wa;
            accC[i] += x * wb;
        }
    }
    float hbv = g_hb[b * M_ + n];
#pragma unroll
    for (int i = 0; i < LT / 2; i++) {
        int l = l0 + 2 * i + lg;
        g_A[((size_t)b * L_ + l) * M_ + n] = accA[i];
        g_C[((size_t)b * L_ + l) * M_ + n] = accC[i] + hbv;
    }
}

// =================================================================================
// Pack W2/W3/W4 into fp16 hi/lo fragment uint4s:
//   g_wpack2[layer][n*32 + slot] = {wh(kw=8c+t), wh(8c+4+t), wl(8c+t), wl(8c+4+t)}
//   slot = (c*4+t) ^ ((n&1)*4)
// where word kw covers weights k = 2kw, 2kw+1 of column n.
// W = Wh + Wl exactly to ~2^-22, so 2 MMAs with full-precision activations' hi
// reproduce A_h * W exactly; only activation rounding (~2^-11, random) is dropped.
// =================================================================================
__global__ void __launch_bounds__(256) pack_weights(
    const float* __restrict__ W2, const float* __restrict__ W3,
    const float* __restrict__ W4)
{
    int idx = blockIdx.x * 256 + threadIdx.x;       // 0 .. 12287
    if (idx >= 3 * 128 * 32) return;
    int layer = idx >> 12;
    int rem   = idx & 4095;
    int n = rem >> 5;
    int s = rem & 31;
    int c = s >> 2;
    int t = s & 3;
    const float* W = layer == 0 ? W2 : (layer == 1 ? W3 : W4);

    uint32_t hw[2], lw[2];
#pragma unroll
    for (int j = 0; j < 2; j++) {
        int kw = 8 * c + 4 * j + t;
        float w0 = W[(size_t)(2 * kw) * 128 + n];
        float w1 = W[(size_t)(2 * kw + 1) * 128 + n];
        __half h0 = __float2half_rn(w0);
        __half h1 = __float2half_rn(w1);
        float r0 = w0 - __half2float(h0);
        float r1 = w1 - __half2float(h1);
        hw[j] = pack_h2(__half2float(h0), __half2float(h1));
        lw[j] = pack_h2(r0, r1);
    }
    int slot = (c * 4 + t) ^ ((n & 1) * 4);
    g_wpack2[layer][n * 32 + slot] = make_uint4(hw[0], hw[1], lw[0], lw[1]);
}

// =================================================================================
// Tensor-core pairwise relation kernel — fp16 2-term split.
// Per inner group: ONE LDS.128 feeds 2 MMAs (Ah*Wh + Ah*Wl = Ah*W).
// =================================================================================
constexpr int SMEM_PW = 128 * 32 * 16;   // 65,536 B

DEV_INLINE void stageW(uint4* smW, int layer, int tid) {
    const uint4* src = g_wpack2[layer];   // 4096 uint4, linear
#pragma unroll
    for (int it = 0; it < 16; it++)
        smW[it * 256 + tid] = src[it * 256 + tid];
}

__global__ void __launch_bounds__(256) pairwise_mma(
    const float* __restrict__ b2, const float* __restrict__ b3,
    const float* __restrict__ b4)
{
    extern __shared__ char smraw[];
    uint4* smW    = (uint4*)smraw;
    float* s_part = (float*)smraw;      // reused after final sync

    const int tile = blockIdx.x;
    const int b    = blockIdx.y;
    const int row0 = tile * 128;
    const int tid  = threadIdx.x;
    const int w    = tid >> 5;
    const int lane = tid & 31;
    const int g    = lane >> 2;
    const int t    = lane & 3;

    // ---- build layer-1 A fragments from global: g1 = lrelu(C_i + A_j), fp16 ----
    uint32_t Ah[8][4];
    const int r0 = row0 + 16 * w + g;
    const int r1 = r0 + 8;
    {
        int rc0 = r0 < NPAIR ? r0 : 0;
        int rc1 = r1 < NPAIR ? r1 : 0;
        int i0 = rc0 / 100, j0 = rc0 - (rc0 / 100) * 100;
        int i1 = rc1 / 100, j1 = rc1 - (rc1 / 100) * 100;
        const float2* C0 = (const float2*)(g_C + ((size_t)b * L_ + i0) * M_);
        const float2* A0 = (const float2*)(g_A + ((size_t)b * L_ + j0) * M_);
        const float2* C1 = (const float2*)(g_C + ((size_t)b * L_ + i1) * M_);
        const float2* A1 = (const float2*)(g_A + ((size_t)b * L_ + j1) * M_);
#pragma unroll
        for (int c = 0; c < 8; c++) {
            int idx = 8 * c + t;
            float2 cc, aa;
            cc = C0[idx];     aa = A0[idx];
            Ah[c][0] = pack_h2(lrelu(cc.x + aa.x), lrelu(cc.y + aa.y));
            cc = C1[idx];     aa = A1[idx];
            Ah[c][1] = pack_h2(lrelu(cc.x + aa.x), lrelu(cc.y + aa.y));
            cc = C0[idx + 4]; aa = A0[idx + 4];
            Ah[c][2] = pack_h2(lrelu(cc.x + aa.x), lrelu(cc.y + aa.y));
            cc = C1[idx + 4]; aa = A1[idx + 4];
            Ah[c][3] = pack_h2(lrelu(cc.x + aa.x), lrelu(cc.y + aa.y));
        }
    }

    stageW(smW, 0, tid);
    __syncthreads();

#pragma unroll
    for (int layer = 0; layer < 3; layer++) {
        float acc[16][4];
#pragma unroll
        for (int nt = 0; nt < 16; nt++)
#pragma unroll
            for (int q = 0; q < 4; q++) acc[nt][q] = 0.f;

#pragma unroll
        for (int c = 0; c < 8; c++) {
            const int base_slot = c * 4 + t;
#pragma unroll
            for (int nt = 0; nt < 16; nt++) {
                const int n = nt * 8 + g;
                uint4 f4 = smW[n * 32 + (base_slot ^ ((n & 1) * 4))];
                mma16816_f16(acc[nt], Ah[c], f4.x, f4.y);   // Ah * Wh
                mma16816_f16(acc[nt], Ah[c], f4.z, f4.w);   // Ah * Wl
            }
        }

        if (layer < 2) {
            const float* bias = layer == 0 ? b2 : b3;
            // epilogue in registers: D-frag -> bias+lrelu -> fp16 -> next A-frag
#pragma unroll
            for (int nt = 0; nt < 16; nt++) {
                int col = nt * 8 + 2 * t;
                float bb0 = __ldg(bias + col);
                float bb1 = __ldg(bias + col + 1);
                float z0 = lrelu(acc[nt][0] + bb0);
                float z1 = lrelu(acc[nt][1] + bb1);
                float z2 = lrelu(acc[nt][2] + bb0);
                float z3 = lrelu(acc[nt][3] + bb1);
                int c2  = nt >> 1;
                int off = (nt & 1) * 2;
                Ah[c2][off]     = pack_h2(z0, z1);
                Ah[c2][off + 1] = pack_h2(z2, z3);
            }
            __syncthreads();              // everyone done reading W[layer]
            stageW(smW, layer + 1, tid);
            __syncthreads();
        } else {
            __syncthreads();              // done reading W3; smem now partials
            const bool live0 = r0 < NPAIR;
            const bool live1 = r1 < NPAIR;
#pragma unroll
            for (int nt = 0; nt < 16; nt++) {
                int col = nt * 8 + 2 * t;
                float bb0 = __ldg(b4 + col);
                float bb1 = __ldg(b4 + col + 1);
                float z0 = live0 ? lrelu(acc[nt][0] + bb0) : 0.f;
                float z1 = live0 ? lrelu(acc[nt][1] + bb1) : 0.f;
                float z2 = live1 ? lrelu(acc[nt][2] + bb0) : 0.f;
                float z3 = live1 ? lrelu(acc[nt][3] + bb1) : 0.f;
                float v0 = z0 + z2;
                float v1 = z1 + z3;
#pragma unroll
                for (int o = 4; o < 32; o <<= 1) {
                    v0 += __shfl_xor_sync(0xffffffffu, v0, o);
                    v1 += __shfl_xor_sync(0xffffffffu, v1, o);
                }
                if (g == 0) {
                    s_part[w * 128 + col]     = v0;
                    s_part[w * 128 + col + 1] = v1;
                }
            }
            __syncthreads();
            if (tid < 128) {
                float ss = 0.f;
#pragma unroll
                for (int ww = 0; ww < 8; ww++) ss += s_part[ww * 128 + tid];
                g_part[((size_t)b * NTILE + tile) * M_ + tid] = ss;
            }
        }
    }
}

// =================================================================================
// Final decoder (unchanged)
// =================================================================================
__global__ void __launch_bounds__(128) final_kernel(
    const float* __restrict__ F1, const float* __restrict__ fb1,
    const float* __restrict__ F2, const float* __restrict__ fb2,
    float* __restrict__ out)
{
    const int b = blockIdx.x;
    const int t = threadIdx.x;
    __shared__ float s_s[M_], t_s[M_];

    float acc = 0.f;
    for (int i = 0; i < NTILE; i++)
        acc += g_part[((size_t)b * NTILE + i) * M_ + t];
    s_s[t] = acc;
    __syncthreads();

    float a2 = fb1[t];
#pragma unroll 4
    for (int k = 0; k < M_; k++) a2 += s_s[k] * F1[(size_t)k * M_ + t];
    t_s[t] = lrelu(a2);
    __syncthreads();

    for (int m = t; m < 512; m += 128) {
        float a3 = fb2[m];
#pragma unroll 4
        for (int k = 0; k < M_; k++) a3 += t_s[k] * F2[(size_t)k * 512 + m];
        out[(size_t)b * 512 + m] = lrelu(a3);
    }
}

// =================================================================================
// launcher
// =================================================================================
extern "C" void kernel_launch(void* const* d_in, const int* in_sizes, int n_in,
                              void* d_out, int out_size)
{
    (void)in_sizes; (void)n_in; (void)out_size;

    const float* x   = (const float*)d_in[0];
    const float* h   = (const float*)d_in[1];
    const float* cw1 = (const float*)d_in[2];
    const float* cb1 = (const float*)d_in[3];
    const float* ga1 = (const float*)d_in[4];
    const float* be1 = (const float*)d_in[5];
    const float* cw2 = (const float*)d_in[6];
    const float* cb2 = (const float*)d_in[7];
    const float* ga2 = (const float*)d_in[8];
    const float* be2 = (const float*)d_in[9];
    const float* cw3 = (const float*)d_in[10];
    const float* cb3 = (const float*)d_in[11];
    const float* ga3 = (const float*)d_in[12];
    const float* be3 = (const float*)d_in[13];
    const float* cw4 = (const float*)d_in[14];
    const float* cb4 = (const float*)d_in[15];
    const float* ga4 = (const float*)d_in[16];
    const float* be4 = (const float*)d_in[17];
    const float* W1  = (const float*)d_in[18];
    const float* b1  = (const float*)d_in[19];
    const float* W2  = (const float*)d_in[20];
    const float* b2  = (const float*)d_in[21];
    const float* W3  = (const float*)d_in[22];
    const float* b3  = (const float*)d_in[23];
    const float* W4  = (const float*)d_in[24];
    const float* b4  = (const float*)d_in[25];
    const float* F1  = (const float*)d_in[26];
    const float* fb1 = (const float*)d_in[27];
    const float* F2  = (const float*)d_in[28];
    const float* fb2 = (const float*)d_in[29];
    float* out = (float*)d_out;

    dim3 cgrid(B_, F_ / FT);

    // conv / BN stack (R4 conv, proven)
    conv_kernel<E_, true ><<<cgrid, 128>>>(x, 0, 0, cw1, cb1, 0);
    stats_kernel<<<F_, 128>>>(0, 0, ga1, be1);
    conv_kernel<F_, false><<<cgrid, 128>>>(nullptr, 0, 0, cw2, cb2, 1);
    stats_kernel<<<F_, 128>>>(1, 1, ga2, be2);
    conv_kernel<F_, false><<<cgrid, 128>>>(nullptr, 1, 1, cw3, cb3, 0);
    stats_kernel<<<F_, 128>>>(0, 2, ga3, be3);
    conv_kernel<F_, false><<<cgrid, 128>>>(nullptr, 0, 2, cw4, cb4, 1);
    stats_kernel<<<F_, 128>>>(1, 3, ga4, be4);

    // fp16 hi/lo weight prep
    pack_weights<<<48, 256>>>(W2, W3, W4);

    // projections
    hb_kernel<<<B_, 128>>>(h, W1, b1);
    ac_kernel<<<dim3(B_, L_ / LT), 256>>>(W1);

    // tensor-core pairwise chain (fp16 2-term: 2 MMAs per fragment load)
    cudaFuncSetAttribute(pairwise_mma,
                         cudaFuncAttributeMaxDynamicSharedMemorySize, SMEM_PW);
    pairwise_mma<<<dim3(NTILE, B_), 256, SMEM_PW>>>(b2, b3, b4);

    // decoder
    final_kernel<<<B_, 128>>>(F1, fb1, F2, fb2, out);
}